// round 3
// baseline (speedup 1.0000x reference)
#include <cuda_runtime.h>
#include <cstdint>
#include <cstddef>

// ---------------- dims ----------------
#define C2_ 32
#define C1_ 64
#define T_  2048
#define AVGF_ 32
#define SEG_ 64
#define M_  2048
#define HA_ 16
#define DH_ 128

// ---------------- scratch (device globals; no allocs allowed) ----------------
__device__ float g_s   [AVGF_ * M_];
__device__ float g_y   [AVGF_ * M_];
__device__ float g_imv [AVGF_ * M_];
__device__ float g_h   [AVGF_ * 4 * M_];
__device__ float g_altx[AVGF_ * M_];
__device__ float g_part[2097152];   // max split-K partials: 8*32*6144 = 1.57M floats

// ---------------- helpers ----------------
__device__ __forceinline__ void cp16(float* sdst, const float* gsrc) {
    uint32_t d = (uint32_t)__cvta_generic_to_shared(sdst);
    asm volatile("cp.async.cg.shared.global [%0], [%1], 16;" :: "r"(d), "l"(gsrc));
}
// 3xTF32 split: hi = f truncated to tf32 (exact); lo = f - hi (exact FADD).
__device__ __forceinline__ void split_tf32(float f, uint32_t& hi, uint32_t& lo) {
    hi = __float_as_uint(f) & 0xffffe000u;
    lo = __float_as_uint(f - __uint_as_float(hi));
}
__device__ __forceinline__ void mma8(float* c,
    uint32_t a0, uint32_t a1, uint32_t a2, uint32_t a3, uint32_t b0, uint32_t b1) {
    asm volatile(
        "mma.sync.aligned.m16n8k8.row.col.f32.tf32.tf32.f32 "
        "{%0,%1,%2,%3},{%4,%5,%6,%7},{%8,%9},{%0,%1,%2,%3};"
        : "+f"(c[0]), "+f"(c[1]), "+f"(c[2]), "+f"(c[3])
        : "r"(a0), "r"(a1), "r"(a2), "r"(a3), "r"(b0), "r"(b1));
}

// ---------------- prep: segment-mean -> altx [32, 2048] ----------------
__global__ void prep_kernel(const float* __restrict__ x, float* __restrict__ altx) {
    int i = blockIdx.x, c1 = blockIdx.y;
    int t = threadIdx.x;             // 256
    int c2 = t >> 3, l8 = t & 7;
    const float4* p = (const float4*)(x + ((size_t)(c2 * C1_ + c1)) * T_ + i * SEG_ + l8 * 8);
    float4 a = p[0], b = p[1];
    float s = a.x + a.y + a.z + a.w + b.x + b.y + b.z + b.w;
    s += __shfl_down_sync(0xffffffffu, s, 4);
    s += __shfl_down_sync(0xffffffffu, s, 2);
    s += __shfl_down_sync(0xffffffffu, s, 1);
    if (l8 == 0) altx[i * M_ + c1 * C2_ + c2] = s * (1.f / 64.f);
}

// ---------------- GEMM: P[(seg*32+i)*N + n] = sum_k W[n][k]*A[i][k]  (3xTF32) ----
// 4-stage cp.async pipeline, KSTEP=32.
#define WST2 36
#define NSTG 4
__global__ __launch_bounds__(256) void gemm_tc(
    const float* __restrict__ W, const float* __restrict__ A,
    float* __restrict__ P, int N, int K, int Kc)
{
    extern __shared__ float sm[];
    float* sW = sm;                        // NSTG * 128*WST2
    float* sA = sm + NSTG * 128 * WST2;    // NSTG * 32*WST2
    const int tid = threadIdx.x;
    const int nbase = blockIdx.x * 128;
    const int kstart = blockIdx.y * Kc;
    const int iters = Kc >> 5;             // KSTEP = 32

    float acc[4][4];
#pragma unroll
    for (int i = 0; i < 4; i++)
#pragma unroll
        for (int j = 0; j < 4; j++) acc[i][j] = 0.f;

    const int w = tid >> 5, lane = tid & 31;
    const int g = lane >> 2, tg = lane & 3;
    const int n0 = w * 16;

    auto load_stage = [&](int st, int k0) {
        float* wd = sW + st * (128 * WST2);
        const float* Wg = W + (size_t)nbase * K + k0;
#pragma unroll
        for (int j = 0; j < 4; j++) {
            int c = tid + j * 256;
            int n = c >> 3, q = (c & 7) << 2;
            cp16(wd + n * WST2 + q, Wg + (size_t)n * K + q);
        }
        float* ad = sA + st * (32 * WST2);
        const float* Ag = A + k0;
        {
            int n = tid >> 3, q = (tid & 7) << 2;
            cp16(ad + n * WST2 + q, Ag + (size_t)n * K + q);
        }
    };

    // prefetch 3 stages (commit 3 groups, possibly empty at tail)
#pragma unroll
    for (int s = 0; s < 3; s++) {
        if (s < iters) load_stage(s, kstart + (s << 5));
        asm volatile("cp.async.commit_group;" ::: "memory");
    }

    for (int it = 0; it < iters; it++) {
        asm volatile("cp.async.wait_group 2;" ::: "memory");
        __syncthreads();
        // issue next stage's loads (targets stage consumed 1 iter ago; sync above
        // guarantees all warps finished it). Commit EVERY iter to keep group count aligned.
        if (it + 3 < iters) load_stage((it + 3) & 3, kstart + ((it + 3) << 5));
        asm volatile("cp.async.commit_group;" ::: "memory");

        const float* wbs  = sW + (it & 3) * (128 * WST2);
        const float* abs_ = sA + (it & 3) * (32 * WST2);
#pragma unroll
        for (int k8 = 0; k8 < 4; k8++) {
            const float* ab = abs_ + (k8 << 3);
            float af[8];
            af[0] = ab[g * WST2 + tg];
            af[1] = ab[(g + 8) * WST2 + tg];
            af[2] = ab[g * WST2 + tg + 4];
            af[3] = ab[(g + 8) * WST2 + tg + 4];
            af[4] = ab[(g + 16) * WST2 + tg];
            af[5] = ab[(g + 24) * WST2 + tg];
            af[6] = ab[(g + 16) * WST2 + tg + 4];
            af[7] = ab[(g + 24) * WST2 + tg + 4];
            uint32_t ah[8], al[8];
#pragma unroll
            for (int j = 0; j < 8; j++) split_tf32(af[j], ah[j], al[j]);

            const float* wb = wbs + (k8 << 3);
            float bf[4];
            bf[0] = wb[(n0 + g) * WST2 + tg];
            bf[1] = wb[(n0 + g) * WST2 + tg + 4];
            bf[2] = wb[(n0 + 8 + g) * WST2 + tg];
            bf[3] = wb[(n0 + 8 + g) * WST2 + tg + 4];
            uint32_t bh[4], bl[4];
#pragma unroll
            for (int j = 0; j < 4; j++) split_tf32(bf[j], bh[j], bl[j]);

            mma8(acc[0], ah[0], ah[1], ah[2], ah[3], bh[0], bh[1]);
            mma8(acc[1], ah[4], ah[5], ah[6], ah[7], bh[0], bh[1]);
            mma8(acc[2], ah[0], ah[1], ah[2], ah[3], bh[2], bh[3]);
            mma8(acc[3], ah[4], ah[5], ah[6], ah[7], bh[2], bh[3]);

            mma8(acc[0], al[0], al[1], al[2], al[3], bh[0], bh[1]);
            mma8(acc[1], al[4], al[5], al[6], al[7], bh[0], bh[1]);
            mma8(acc[2], al[0], al[1], al[2], al[3], bh[2], bh[3]);
            mma8(acc[3], al[4], al[5], al[6], al[7], bh[2], bh[3]);

            mma8(acc[0], ah[0], ah[1], ah[2], ah[3], bl[0], bl[1]);
            mma8(acc[1], ah[4], ah[5], ah[6], ah[7], bl[0], bl[1]);
            mma8(acc[2], ah[0], ah[1], ah[2], ah[3], bl[2], bl[3]);
            mma8(acc[3], ah[4], ah[5], ah[6], ah[7], bl[2], bl[3]);
        }
        __syncthreads();
    }

    float* Pb = P + (size_t)(blockIdx.y * 32) * N + nbase;
#pragma unroll
    for (int t4 = 0; t4 < 4; t4++) {
        int r = g + ((t4 & 1) << 4);
        int c = n0 + ((t4 >> 1) << 3) + (tg << 1);
        *(float2*)(Pb + (size_t)r * N + c) = make_float2(acc[t4][0], acc[t4][1]);
        *(float2*)(Pb + (size_t)(r + 8) * N + c) = make_float2(acc[t4][2], acc[t4][3]);
    }
}

// ---------------- fused reduce (+bias/residual) + LayerNorm, N=2048 ----------
// mode 0: v = sum + sinusoidal bias; sout = v; yout = LN(v)*g+b
// mode 1: v = sum + extra[n] (bias);  sout = v; yout = LN(v)*g+b
// mode 2: v = sum + extra[i*2048+n] (residual); yout = LN(v)*g+b + v  (sout unused)
__global__ __launch_bounds__(256) void reduce_ln(
    const float* __restrict__ P, int S, int mode,
    const float* __restrict__ extra, const float* __restrict__ gw, const float* __restrict__ bw,
    float* __restrict__ sout, float* __restrict__ yout)
{
    __shared__ float red[16];
    __shared__ float stats[2];
    int i = blockIdx.x, t = threadIdx.x;
    int c0 = t << 2, c1 = 1024 + (t << 2);

    float4 v0 = make_float4(0.f, 0.f, 0.f, 0.f);
    float4 v1 = make_float4(0.f, 0.f, 0.f, 0.f);
    for (int s = 0; s < S; s++) {
        const float* row = P + (size_t)(s * 32 + i) * M_;
        float4 p0 = *(const float4*)(row + c0);
        float4 p1 = *(const float4*)(row + c1);
        v0.x += p0.x; v0.y += p0.y; v0.z += p0.z; v0.w += p0.w;
        v1.x += p1.x; v1.y += p1.y; v1.z += p1.z; v1.w += p1.w;
    }
    if (mode == 0) {
        float* vv0 = &v0.x; float* vv1 = &v1.x;
#pragma unroll
        for (int c = 0; c < 4; c++) {
            int col = c0 + c;
            float ang = (float)i * exp2f((float)(col & ~1) * (-13.28771237954945f / 1024.f));
            vv0[c] += (col & 1) ? cosf(ang) : sinf(ang);
            col = c1 + c;
            ang = (float)i * exp2f((float)(col & ~1) * (-13.28771237954945f / 1024.f));
            vv1[c] += (col & 1) ? cosf(ang) : sinf(ang);
        }
    } else if (mode == 1) {
        float4 b0 = *(const float4*)(extra + c0), b1 = *(const float4*)(extra + c1);
        v0.x += b0.x; v0.y += b0.y; v0.z += b0.z; v0.w += b0.w;
        v1.x += b1.x; v1.y += b1.y; v1.z += b1.z; v1.w += b1.w;
    } else {
        const float* res = extra + (size_t)i * M_;
        float4 r0 = *(const float4*)(res + c0), r1 = *(const float4*)(res + c1);
        v0.x += r0.x; v0.y += r0.y; v0.z += r0.z; v0.w += r0.w;
        v1.x += r1.x; v1.y += r1.y; v1.z += r1.z; v1.w += r1.w;
    }

    float s = v0.x + v0.y + v0.z + v0.w + v1.x + v1.y + v1.z + v1.w;
    float q = v0.x * v0.x + v0.y * v0.y + v0.z * v0.z + v0.w * v0.w
            + v1.x * v1.x + v1.y * v1.y + v1.z * v1.z + v1.w * v1.w;
#pragma unroll
    for (int o = 16; o > 0; o >>= 1) {
        s += __shfl_down_sync(0xffffffffu, s, o);
        q += __shfl_down_sync(0xffffffffu, q, o);
    }
    int w = t >> 5, l = t & 31;
    if (l == 0) { red[w] = s; red[8 + w] = q; }
    __syncthreads();
    if (t == 0) {
        float S_ = 0.f, Q_ = 0.f;
        for (int k = 0; k < 8; k++) { S_ += red[k]; Q_ += red[8 + k]; }
        float mean = S_ * (1.f / (float)M_);
        float var = Q_ * (1.f / (float)M_) - mean * mean;
        stats[0] = mean;
        stats[1] = rsqrtf(var + 1e-5f);
    }
    __syncthreads();
    float mean = stats[0], rstd = stats[1];

    if (mode < 2) {
        float* so = sout + (size_t)i * M_;
        *(float4*)(so + c0) = v0;
        *(float4*)(so + c1) = v1;
    }
    float resmul = (mode == 2) ? 1.f : 0.f;
    float* yo = yout + (size_t)i * M_;
    {
        float4 gv = *(const float4*)(gw + c0), bv = *(const float4*)(bw + c0), o;
        o.x = (v0.x - mean) * rstd * gv.x + bv.x + resmul * v0.x;
        o.y = (v0.y - mean) * rstd * gv.y + bv.y + resmul * v0.y;
        o.z = (v0.z - mean) * rstd * gv.z + bv.z + resmul * v0.z;
        o.w = (v0.w - mean) * rstd * gv.w + bv.w + resmul * v0.w;
        *(float4*)(yo + c0) = o;
    }
    {
        float4 gv = *(const float4*)(gw + c1), bv = *(const float4*)(bw + c1), o;
        o.x = (v1.x - mean) * rstd * gv.x + bv.x + resmul * v1.x;
        o.y = (v1.y - mean) * rstd * gv.y + bv.y + resmul * v1.y;
        o.z = (v1.z - mean) * rstd * gv.z + bv.z + resmul * v1.z;
        o.w = (v1.w - mean) * rstd * gv.w + bv.w + resmul * v1.w;
        *(float4*)(yo + c1) = o;
    }
}

// ---------------- fused qkv-reduce + scalar attention + cumsum ---------------
// P: qkv partials [8 segs][32 rows][6144]; imv [32][2048]
__global__ void attn_fused(const float* __restrict__ P, float* __restrict__ imv)
{
    int h = blockIdx.x;          // 16
    int t = threadIdx.x;         // 128
    int w = t >> 5, l = t & 31;
    __shared__ float rsa[AVGF_];
    for (int i = w; i < AVGF_; i += 4) {
        float dot = 0.f;
#pragma unroll
        for (int dd = 0; dd < 4; dd++) {
            int d = l + dd * 32;
            float qv = 0.f, kv = 0.f;
#pragma unroll
            for (int s = 0; s < 8; s++) {
                const float* row = P + (size_t)(s * 32 + i) * (3 * M_) + h * DH_ + d;
                qv += row[0];
                kv += row[M_];
            }
            dot += qv * kv;
        }
#pragma unroll
        for (int o = 16; o > 0; o >>= 1) dot += __shfl_down_sync(0xffffffffu, dot, o);
        if (l == 0) rsa[i] = dot * 0.08838834764831845f;  // 1/sqrt(128)
    }
    __syncthreads();
    float run = 0.f;
#pragma unroll
    for (int i = 0; i < AVGF_; i++) {
        float vv = 0.f;
#pragma unroll
        for (int s = 0; s < 8; s++)
            vv += P[(size_t)(s * 32 + i) * (3 * M_) + 2 * M_ + h * DH_ + t];
        run += rsa[i] * vv;
        imv[(size_t)i * M_ + h * DH_ + t] = run;
    }
}

// ---------------- reduce + bias + exact GELU (fc1, N=8192, S=4) --------------
__global__ void reduce_gelu(const float* __restrict__ P,
                            const float* __restrict__ bias, float* __restrict__ out)
{
    int idx = blockIdx.x * blockDim.x + threadIdx.x;
    int e = idx << 2;
    int i = e >> 13, n = e & 8191;
    float v[4] = {0.f, 0.f, 0.f, 0.f};
#pragma unroll
    for (int s = 0; s < 4; s++) {
        const float4 p = *(const float4*)(P + (size_t)(s * 32 + i) * 8192 + n);
        v[0] += p.x; v[1] += p.y; v[2] += p.z; v[3] += p.w;
    }
#pragma unroll
    for (int c = 0; c < 4; c++) {
        float tt = v[c] + bias[n + c];
        v[c] = 0.5f * tt * (1.f + erff(tt * 0.7071067811865475f));
    }
    *(float4*)(out + e) = make_float4(v[0], v[1], v[2], v[3]);
}

// ---------------- launch ----------------
extern "C" void kernel_launch(void* const* d_in, const int* in_sizes, int n_in,
                              void* d_out, int out_size)
{
    const float* x      = (const float*)d_in[0];
    const float* weight = (const float*)d_in[1];
    const float* Wqkv   = (const float*)d_in[2];
    const float* Wo     = (const float*)d_in[3];
    const float* ln1_g  = (const float*)d_in[4];
    const float* ln1_b  = (const float*)d_in[5];
    const float* ln2_g  = (const float*)d_in[6];
    const float* ln2_b  = (const float*)d_in[7];
    const float* fc1_w  = (const float*)d_in[8];
    const float* fc1_b  = (const float*)d_in[9];
    const float* fc2_w  = (const float*)d_in[10];
    const float* fc2_b  = (const float*)d_in[11];
    float* out = (float*)d_out;

    const int SMEMSZ = (NSTG * 128 * WST2 + NSTG * 32 * WST2) * (int)sizeof(float); // 92160
    cudaFuncSetAttribute(gemm_tc, cudaFuncAttributeMaxDynamicSharedMemorySize, SMEMSZ);

    float *altx, *sbuf, *ybuf, *imv, *hbuf, *part;
    cudaGetSymbolAddress((void**)&altx, g_altx);
    cudaGetSymbolAddress((void**)&sbuf, g_s);
    cudaGetSymbolAddress((void**)&ybuf, g_y);
    cudaGetSymbolAddress((void**)&imv,  g_imv);
    cudaGetSymbolAddress((void**)&hbuf, g_h);
    cudaGetSymbolAddress((void**)&part, g_part);

    // 1. altx
    prep_kernel<<<dim3(AVGF_, C1_), 256>>>(x, altx);
    // 2. s = altx @ weight^T (+ sin bias), then y = LN1(s)
    gemm_tc<<<dim3(16, 16), 256, SMEMSZ>>>(weight, altx, part, 2048, 2048, 128);
    // 3.
    reduce_ln<<<32, 256>>>(part, 16, 0, nullptr, ln1_g, ln1_b, sbuf, ybuf);

    for (int a = 0; a < 3; a++) {
        // qkv = y @ Wqkv[a]^T   [32, 6144]
        gemm_tc<<<dim3(48, 8), 256, SMEMSZ>>>(Wqkv + (size_t)a * 3 * HA_ * DH_ * M_,
                                              ybuf, part, 6144, 2048, 256);
        // fused qkv-reduce + scalar attn + cumsum -> imv
        attn_fused<<<16, 128>>>(part, imv);
        // s2 = imv @ Wo[a]^T + s ; sbuf = LN2(s2) + s2
        gemm_tc<<<dim3(16, 16), 256, SMEMSZ>>>(Wo + (size_t)a * M_ * M_,
                                               imv, part, 2048, 2048, 128);
        reduce_ln<<<32, 256>>>(part, 16, 2, sbuf, ln2_g, ln2_b, nullptr, sbuf);
        // h = gelu(sbuf @ fc1^T + b1)   [32, 8192]
        gemm_tc<<<dim3(64, 4), 256, SMEMSZ>>>(fc1_w, sbuf, part, 8192, 2048, 512);
        reduce_gelu<<<256, 256>>>(part, fc1_b, hbuf);
        // s = h @ fc2^T + b2 ; y = LN1(s) for next block
        gemm_tc<<<dim3(16, 16), 256, SMEMSZ>>>(fc2_w, hbuf, part, 2048, 8192, 512);
        reduce_ln<<<32, 256>>>(part, 16, 1, fc2_b, ln1_g, ln1_b,
                               (a == 2) ? out : sbuf, ybuf);
    }
}